// round 11
// baseline (speedup 1.0000x reference)
#include <cuda_runtime.h>

// Problem shape (fixed): x[B=64, C=256, H=56, W=56] fp32
#define C_    256
#define B_    64
#define HW4_  784        // float4 per plane
#define NPC_  200704     // B*HW elements per channel
#define EPS_  1e-5f
// Planes with b < KEEP_B are loaded streaming (evict-first) in phase 1;
// planes b >= KEEP_B load evict-normal so they stay L2-resident for phase 2.
// (64-26)=38 planes * 256 ch * 12.25 KB = ~119 MB, just under the 126 MB L2.
#define KEEP_B_ 26

__device__ __forceinline__ float fsum4(const float4 v) { return (v.x + v.y) + (v.z + v.w); }
__device__ __forceinline__ float fsq4 (const float4 v) { return v.x*v.x + v.y*v.y + v.z*v.z + v.w*v.w; }

// ---------------------------------------------------------------------------
// Fully fused BatchNorm: one CTA per channel. No inter-CTA dependency:
// CTA c computes channel-c stats over its 64 planes, then normalizes the
// same 64 planes in REVERSE order so its own L1/L2-resident tail is
// consumed first (L1D persists within a launch; the old 2-kernel split
// forcibly flushed it at the launch boundary).
// ---------------------------------------------------------------------------
__global__ __launch_bounds__(256) void bn_fused_k(const float4* __restrict__ x,
                                                  const float* __restrict__ gamma,
                                                  const float* __restrict__ beta,
                                                  float4* __restrict__ out) {
    const int c = blockIdx.x;        // channel
    const int t = threadIdx.x;

    // ---------------- Phase 1: per-channel sum / sumsq over 64 planes ------
    float s = 0.f, q = 0.f;

    // Front planes: streaming loads (these lines cannot survive to phase 2).
    for (int b = 0; b < KEEP_B_; b++) {
        const float4* p = x + ((size_t)(b * C_ + c)) * HW4_;
        float4 v0 = __ldcs(p + t);
        float4 v1 = __ldcs(p + t + 256);
        float4 v2 = __ldcs(p + t + 512);
        s += fsum4(v0) + fsum4(v1) + fsum4(v2);
        q += fsq4 (v0) + fsq4 (v1) + fsq4 (v2);
        if (t < 16) {
            float4 v3 = __ldcs(p + t + 768);
            s += fsum4(v3); q += fsq4(v3);
        }
    }
    // Tail planes: evict-normal -> stay resident in L1/L2 for phase 2.
    for (int b = KEEP_B_; b < B_; b++) {
        const float4* p = x + ((size_t)(b * C_ + c)) * HW4_;
        float4 v0 = p[t];
        float4 v1 = p[t + 256];
        float4 v2 = p[t + 512];
        s += fsum4(v0) + fsum4(v1) + fsum4(v2);
        q += fsq4 (v0) + fsq4 (v1) + fsq4 (v2);
        if (t < 16) {
            float4 v3 = p[t + 768];
            s += fsum4(v3); q += fsq4(v3);
        }
    }

    // Block reduction.
    #pragma unroll
    for (int o = 16; o > 0; o >>= 1) {
        s += __shfl_xor_sync(0xffffffffu, s, o);
        q += __shfl_xor_sync(0xffffffffu, q, o);
    }
    __shared__ float ss[8], sq_[8];
    __shared__ float sh_sc, sh_bi;
    const int w = t >> 5, l = t & 31;
    if (l == 0) { ss[w] = s; sq_[w] = q; }
    __syncthreads();
    if (t == 0) {
        float ts = 0.f, tq = 0.f;
        #pragma unroll
        for (int i = 0; i < 8; i++) { ts += ss[i]; tq += sq_[i]; }
        const float inv_n = 1.f / (float)NPC_;
        const float mean  = ts * inv_n;
        const float var   = tq * inv_n - mean * mean;   // biased
        const float sc    = gamma[c] * rsqrtf(var + EPS_);
        sh_sc = sc;
        sh_bi = beta[c] - mean * sc;
    }
    __syncthreads();
    const float sc = sh_sc;
    const float bi = sh_bi;

    // ---------------- Phase 2: normalize, reverse plane order --------------
    // Most recently read planes first: L1 hits for the last ~100 KB, L2 hits
    // for the resident tail, DRAM only for the early (streamed) planes.
    for (int b = B_ - 1; b >= 0; b--) {
        const size_t base = ((size_t)(b * C_ + c)) * HW4_;
        const float4* p = x + base;
        float4* o = out + base;
        float4 v0 = p[t];
        float4 v1 = p[t + 256];
        float4 v2 = p[t + 512];
        v0.x = fmaf(v0.x, sc, bi); v0.y = fmaf(v0.y, sc, bi);
        v0.z = fmaf(v0.z, sc, bi); v0.w = fmaf(v0.w, sc, bi);
        v1.x = fmaf(v1.x, sc, bi); v1.y = fmaf(v1.y, sc, bi);
        v1.z = fmaf(v1.z, sc, bi); v1.w = fmaf(v1.w, sc, bi);
        v2.x = fmaf(v2.x, sc, bi); v2.y = fmaf(v2.y, sc, bi);
        v2.z = fmaf(v2.z, sc, bi); v2.w = fmaf(v2.w, sc, bi);
        __stcs(o + t,       v0);
        __stcs(o + t + 256, v1);
        __stcs(o + t + 512, v2);
        if (t < 16) {
            float4 v3 = p[t + 768];
            v3.x = fmaf(v3.x, sc, bi); v3.y = fmaf(v3.y, sc, bi);
            v3.z = fmaf(v3.z, sc, bi); v3.w = fmaf(v3.w, sc, bi);
            __stcs(o + t + 768, v3);
        }
    }
}

// ---------------------------------------------------------------------------
extern "C" void kernel_launch(void* const* d_in, const int* in_sizes, int n_in,
                              void* d_out, int out_size) {
    const float* x     = (const float*)d_in[0];
    const float* gamma = (const float*)d_in[1];
    const float* beta  = (const float*)d_in[2];
    float* out = (float*)d_out;

    bn_fused_k<<<C_, 256>>>((const float4*)x, gamma, beta, (float4*)out);
}

// round 14
// speedup vs baseline: 1.0464x; 1.0464x over previous
#include <cuda_runtime.h>

// Problem shape (fixed): x[B=64, C=256, H=56, W=56] fp32
#define C_    256
#define B_    64
#define HW4_  784        // float4 per plane
#define NPC_  200704     // B*HW elements per channel
#define EPS_  1e-5f
#define GRID_ 512        // persistent CTAs; 4/SM on 148 SMs -> one wave guaranteed
#define PPC_  32         // planes per CTA (16384 / 512), contiguous
#define KEEPP_ 16        // last 16 planes/CTA load evict-normal (~100 MB chip-wide)
#define NPLANES_ 16384

__device__ float g_ps[NPLANES_ * 8];   // per-plane per-warp partial sums
__device__ float g_pq[NPLANES_ * 8];   // per-plane per-warp partial sumsq
__device__ unsigned long long g_ctr;   // barrier ticket counter (zero-init, monotonic)

__device__ __forceinline__ float fsum4(const float4 v) { return (v.x + v.y) + (v.z + v.w); }
__device__ __forceinline__ float fsq4 (const float4 v) { return v.x*v.x + v.y*v.y + v.z*v.z + v.w*v.w; }

// ---------------------------------------------------------------------------
// Persistent fused BatchNorm. One wave of 512 CTAs; software grid barrier.
// CTA k owns planes [32k, 32k+32) — a contiguous 784 KB chunk; its 32
// channels are (32k & 255) + 0..31 (never crosses a channel-block boundary).
// Co-residency proof: 256 thr (8 warps), ~40 regs, ~300 B smem -> >=4 CTAs/SM
// by every limit; 148 SMs * 4 = 592 >= 512. Barrier is ticket-based and
// monotonic -> safe across graph replays.
// ---------------------------------------------------------------------------
__global__ __launch_bounds__(256) void bn_k(const float4* __restrict__ x,
                                            const float* __restrict__ gamma,
                                            const float* __restrict__ beta,
                                            float4* __restrict__ out) {
    const int t  = threadIdx.x;
    const int w  = t >> 5, l = t & 31;
    const int p0 = blockIdx.x * PPC_;

    // ---------------- Phase 1: per-plane partial sums ----------------------
    #pragma unroll 1
    for (int i = 0; i < PPC_; i++) {
        const float4* p = x + (size_t)(p0 + i) * HW4_;
        float4 v0, v1, v2, v3;
        const bool keep = (i >= PPC_ - KEEPP_);
        if (keep) { v0 = p[t]; v1 = p[t + 256]; v2 = p[t + 512]; }
        else      { v0 = __ldcs(p + t); v1 = __ldcs(p + t + 256); v2 = __ldcs(p + t + 512); }
        float s = fsum4(v0) + fsum4(v1) + fsum4(v2);
        float q = fsq4 (v0) + fsq4 (v1) + fsq4 (v2);
        if (t < 16) {
            v3 = keep ? p[t + 768] : __ldcs(p + t + 768);
            s += fsum4(v3); q += fsq4(v3);
        }
        #pragma unroll
        for (int o = 16; o > 0; o >>= 1) {
            s += __shfl_xor_sync(0xffffffffu, s, o);
            q += __shfl_xor_sync(0xffffffffu, q, o);
        }
        if (l == 0) {
            g_ps[(p0 + i) * 8 + w] = s;
            g_pq[(p0 + i) * 8 + w] = q;
        }
    }

    // ---------------- Grid barrier (self-resetting, replay-safe) -----------
    __threadfence();
    __syncthreads();
    if (t == 0) {
        const unsigned long long r = atomicAdd(&g_ctr, 1ULL);
        const unsigned long long target = (r / GRID_ + 1ULL) * GRID_;
        while (atomicAdd(&g_ctr, 0ULL) < target) __nanosleep(128);
        __threadfence();
    }
    __syncthreads();

    // ---------------- Phase 1.5: scale/bias for this CTA's 32 channels -----
    __shared__ float sc_s[PPC_], bi_s[PPC_];
    {
        const int ch = t >> 3;               // 0..31
        const int j  = t & 7;                // 8 threads per channel
        const int c  = (p0 & (C_ - 1)) + ch;
        float s = 0.f, q = 0.f;
        #pragma unroll 1
        for (int bb = 0; bb < 8; bb++) {
            const int b = j * 8 + bb;
            const int base = (b * C_ + c) * 8;
            #pragma unroll
            for (int ww = 0; ww < 8; ww++) { s += g_ps[base + ww]; q += g_pq[base + ww]; }
        }
        #pragma unroll
        for (int o = 4; o > 0; o >>= 1) {
            s += __shfl_xor_sync(0xffffffffu, s, o);
            q += __shfl_xor_sync(0xffffffffu, q, o);
        }
        if (j == 0) {
            const float inv_n = 1.f / (float)NPC_;
            const float mean  = s * inv_n;
            const float var   = q * inv_n - mean * mean;   // biased
            const float scv   = gamma[c] * rsqrtf(var + EPS_);
            sc_s[ch] = scv;
            bi_s[ch] = beta[c] - mean * scv;
        }
    }
    __syncthreads();

    // ---------------- Phase 2: normalize own planes, REVERSED --------------
    // Same launch => L1D not flushed: most recent planes hit L1, the keep
    // half hits L2 (exact producer-consumer match, no inter-CTA skew).
    #pragma unroll 1
    for (int i = PPC_ - 1; i >= 0; i--) {
        const size_t base = (size_t)(p0 + i) * HW4_;
        const float4* p = x + base;
        float4* o = out + base;
        const float sc = sc_s[i];
        const float bi = bi_s[i];
        float4 v0 = p[t], v1 = p[t + 256], v2 = p[t + 512];
        v0.x = fmaf(v0.x, sc, bi); v0.y = fmaf(v0.y, sc, bi);
        v0.z = fmaf(v0.z, sc, bi); v0.w = fmaf(v0.w, sc, bi);
        v1.x = fmaf(v1.x, sc, bi); v1.y = fmaf(v1.y, sc, bi);
        v1.z = fmaf(v1.z, sc, bi); v1.w = fmaf(v1.w, sc, bi);
        v2.x = fmaf(v2.x, sc, bi); v2.y = fmaf(v2.y, sc, bi);
        v2.z = fmaf(v2.z, sc, bi); v2.w = fmaf(v2.w, sc, bi);
        __stcs(o + t,       v0);
        __stcs(o + t + 256, v1);
        __stcs(o + t + 512, v2);
        if (t < 16) {
            float4 v3 = p[t + 768];
            v3.x = fmaf(v3.x, sc, bi); v3.y = fmaf(v3.y, sc, bi);
            v3.z = fmaf(v3.z, sc, bi); v3.w = fmaf(v3.w, sc, bi);
            __stcs(o + t + 768, v3);
        }
    }
}

// ---------------------------------------------------------------------------
extern "C" void kernel_launch(void* const* d_in, const int* in_sizes, int n_in,
                              void* d_out, int out_size) {
    const float* x     = (const float*)d_in[0];
    const float* gamma = (const float*)d_in[1];
    const float* beta  = (const float*)d_in[2];
    float* out = (float*)d_out;

    bn_k<<<GRID_, 256>>>((const float4*)x, gamma, beta, (float4*)out);
}

// round 15
// speedup vs baseline: 1.2918x; 1.2346x over previous
#include <cuda_runtime.h>

// Problem shape (fixed): x[B=64, C=256, H=56, W=56] fp32
#define C_    256
#define B_    64
#define HW4_  784        // HW/4 (float4 per plane)
#define NPC_  200704     // B*HW elements per channel
#define EPS_  1e-5f
#define N4_   12845056   // total float4 = B*C*HW4
#define NBLK_ 6272       // norm blocks: N4 / 2048
// float4 index where the L2-kept tail begins (~95 MB kept resident).
#define RESIDENT_START_ 6900000

__device__ float g_psum[C_ * B_];
__device__ float g_psq [C_ * B_];
__device__ float g_scale[C_];
__device__ float g_bias [C_];

__device__ __forceinline__ float fsum4(const float4 v)  { return (v.x + v.y) + (v.z + v.w); }
__device__ __forceinline__ float fsq4 (const float4 v)  { return v.x*v.x + v.y*v.y + v.z*v.z + v.w*v.w; }

// ---------------------------------------------------------------------------
// Pass 1: two planes (b, 2c) and (b, 2c+1) per block. 1568 float4, 256 thr.
// Grid (c2 fast, b slow): block execution order ~ linear address order.
// Front region: evict-first streaming. Tail (~95 MB): evict-normal, stays
// L2-resident for the reversed norm pass.
// ---------------------------------------------------------------------------
__global__ __launch_bounds__(256) void reduce_k(const float4* __restrict__ x) {
    const int c2 = blockIdx.x;                  // channel pair index (fast)
    const int b  = blockIdx.y;                  // batch (slow)
    const size_t start4 = ((size_t)b * C_ + 2 * c2) * HW4_;
    const float4* p = x + start4;
    const int t = threadIdx.x;
    const bool keep = (start4 >= (size_t)RESIDENT_START_);

    float4 v0, v1, v2, v3, v4, v5, v6;
    v6 = make_float4(0.f, 0.f, 0.f, 0.f);
    if (keep) {
        v0 = p[t];        v1 = p[t + 256];  v2 = p[t + 512];
        v3 = p[t + 768];  v4 = p[t + 1024]; v5 = p[t + 1280];
        if (t < 32) v6 = p[t + 1536];
    } else {
        v0 = __ldcs(p + t);        v1 = __ldcs(p + t + 256);
        v2 = __ldcs(p + t + 512);  v3 = __ldcs(p + t + 768);
        v4 = __ldcs(p + t + 1024); v5 = __ldcs(p + t + 1280);
        if (t < 32) v6 = __ldcs(p + t + 1536);
    }

    float s0 = fsum4(v0) + fsum4(v1) + fsum4(v2);
    float q0 = fsq4 (v0) + fsq4 (v1) + fsq4 (v2);
    float s1 = fsum4(v4) + fsum4(v5) + fsum4(v6);
    float q1 = fsq4 (v4) + fsq4 (v5) + fsq4 (v6);
    // j=3 straddles the plane boundary at 784: plane0 iff t < 16
    const float s3 = fsum4(v3), q3 = fsq4(v3);
    if (t < 16) { s0 += s3; q0 += q3; } else { s1 += s3; q1 += q3; }

    #pragma unroll
    for (int o = 16; o > 0; o >>= 1) {
        s0 += __shfl_xor_sync(0xffffffffu, s0, o);
        q0 += __shfl_xor_sync(0xffffffffu, q0, o);
        s1 += __shfl_xor_sync(0xffffffffu, s1, o);
        q1 += __shfl_xor_sync(0xffffffffu, q1, o);
    }

    __shared__ float sh[4][8];
    const int w = t >> 5, l = t & 31;
    if (l == 0) { sh[0][w] = s0; sh[1][w] = q0; sh[2][w] = s1; sh[3][w] = q1; }
    __syncthreads();

    if (t < 2) {   // t=0 -> plane0, t=1 -> plane1
        float ts = 0.f, tq = 0.f;
        #pragma unroll
        for (int i = 0; i < 8; i++) { ts += sh[2 * t][i]; tq += sh[2 * t + 1][i]; }
        const int c = 2 * c2 + t;
        g_psum[c * B_ + b] = ts;
        g_psq [c * B_ + b] = tq;
    }
}

// ---------------------------------------------------------------------------
// Fold partials -> fused scale/bias. One block of 256 threads.
// ---------------------------------------------------------------------------
__global__ __launch_bounds__(256) void finalize_k(const float* __restrict__ gamma,
                                                  const float* __restrict__ beta) {
    const int c = threadIdx.x;
    float s = 0.f, sq = 0.f;
    #pragma unroll
    for (int b = 0; b < B_; b++) {
        s  += g_psum[c * B_ + b];
        sq += g_psq [c * B_ + b];
    }
    const float inv_n = 1.f / (float)NPC_;
    const float mean  = s * inv_n;
    const float var   = sq * inv_n - mean * mean;
    const float sc    = gamma[c] * rsqrtf(var + EPS_);
    g_scale[c] = sc;
    g_bias[c]  = beta[c] - mean * sc;
}

// ---------------------------------------------------------------------------
// Pass 2: flat elementwise, REVERSED block order (consume the L2-kept tail
// first). Reads __ldcs (hit-demote / no-pollute). Stores WRITE-THROUGH
// (__stwt): no L2 write-allocate, so the out stream cannot displace the
// keep set. 6272 blocks x 256 threads x 8 float4, no tail predication.
// ---------------------------------------------------------------------------
__global__ __launch_bounds__(256) void norm_k(const float4* __restrict__ x,
                                              float4* __restrict__ out) {
    const int base = (NBLK_ - 1 - (int)blockIdx.x) * 2048 + (int)threadIdx.x;

    float4 v[8];
    #pragma unroll
    for (int j = 0; j < 8; j++) v[j] = __ldcs(x + base + 256 * j);

    #pragma unroll
    for (int j = 0; j < 8; j++) {
        const int idx = base + 256 * j;
        const int c   = (idx / HW4_) & (C_ - 1);      // plane mod C
        const float sc = g_scale[c];
        const float bi = g_bias[c];
        v[j].x = fmaf(v[j].x, sc, bi);
        v[j].y = fmaf(v[j].y, sc, bi);
        v[j].z = fmaf(v[j].z, sc, bi);
        v[j].w = fmaf(v[j].w, sc, bi);
        __stwt(out + idx, v[j]);
    }
}

// ---------------------------------------------------------------------------
extern "C" void kernel_launch(void* const* d_in, const int* in_sizes, int n_in,
                              void* d_out, int out_size) {
    const float* x     = (const float*)d_in[0];
    const float* gamma = (const float*)d_in[1];
    const float* beta  = (const float*)d_in[2];
    float* out = (float*)d_out;

    dim3 rgrid(C_ / 2, B_);     // c2 fast, b slow -> execution ~ address order
    reduce_k<<<rgrid, 256>>>((const float4*)x);
    finalize_k<<<1, C_>>>(gamma, beta);
    norm_k<<<NBLK_, 256>>>((const float4*)x, (float4*)out);
}

// round 17
// speedup vs baseline: 1.3539x; 1.0481x over previous
#include <cuda_runtime.h>

// Problem shape (fixed): x[B=64, C=256, H=56, W=56] fp32
#define C_    256
#define B_    64
#define HW4_  784        // HW/4 (float4 per plane)
#define NPC_  200704     // B*HW elements per channel
#define EPS_  1e-5f
#define N4_   12845056   // total float4 = B*C*HW4
#define NBLK_ 6272       // norm blocks: N4 / 2048
// float4 index where the L2-kept tail begins. 7212800 = 1568*4600 (multiple
// of the 2-plane reduce block, so no reduce block straddles it). Keep set =
// (12845056-7212800)*16B = 90.1 MB -> ~36 MB L2 slack for store transients.
#define RESIDENT_START_ 7212800

__device__ float g_psum[C_ * B_];
__device__ float g_psq [C_ * B_];
__device__ float g_scale[C_];
__device__ float g_bias [C_];

__device__ __forceinline__ float fsum4(const float4 v)  { return (v.x + v.y) + (v.z + v.w); }
__device__ __forceinline__ float fsq4 (const float4 v)  { return v.x*v.x + v.y*v.y + v.z*v.z + v.w*v.w; }

// ---------------------------------------------------------------------------
// Pass 1: two planes (b, 2c) and (b, 2c+1) per block. 1568 float4, 256 thr.
// Grid (c2 fast, b slow): block execution order ~ linear address order.
// Front region: evict-first streaming. Tail (~90 MB): evict-normal, stays
// L2-resident for the reversed norm pass.
// ---------------------------------------------------------------------------
__global__ __launch_bounds__(256) void reduce_k(const float4* __restrict__ x) {
    const int c2 = blockIdx.x;                  // channel pair index (fast)
    const int b  = blockIdx.y;                  // batch (slow)
    const size_t start4 = ((size_t)b * C_ + 2 * c2) * HW4_;
    const float4* p = x + start4;
    const int t = threadIdx.x;
    const bool keep = (start4 >= (size_t)RESIDENT_START_);

    float4 v0, v1, v2, v3, v4, v5, v6;
    v6 = make_float4(0.f, 0.f, 0.f, 0.f);
    if (keep) {
        v0 = p[t];        v1 = p[t + 256];  v2 = p[t + 512];
        v3 = p[t + 768];  v4 = p[t + 1024]; v5 = p[t + 1280];
        if (t < 32) v6 = p[t + 1536];
    } else {
        v0 = __ldcs(p + t);        v1 = __ldcs(p + t + 256);
        v2 = __ldcs(p + t + 512);  v3 = __ldcs(p + t + 768);
        v4 = __ldcs(p + t + 1024); v5 = __ldcs(p + t + 1280);
        if (t < 32) v6 = __ldcs(p + t + 1536);
    }

    float s0 = fsum4(v0) + fsum4(v1) + fsum4(v2);
    float q0 = fsq4 (v0) + fsq4 (v1) + fsq4 (v2);
    float s1 = fsum4(v4) + fsum4(v5) + fsum4(v6);
    float q1 = fsq4 (v4) + fsq4 (v5) + fsq4 (v6);
    // j=3 straddles the plane boundary at 784: plane0 iff t < 16
    const float s3 = fsum4(v3), q3 = fsq4(v3);
    if (t < 16) { s0 += s3; q0 += q3; } else { s1 += s3; q1 += q3; }

    #pragma unroll
    for (int o = 16; o > 0; o >>= 1) {
        s0 += __shfl_xor_sync(0xffffffffu, s0, o);
        q0 += __shfl_xor_sync(0xffffffffu, q0, o);
        s1 += __shfl_xor_sync(0xffffffffu, s1, o);
        q1 += __shfl_xor_sync(0xffffffffu, q1, o);
    }

    __shared__ float sh[4][8];
    const int w = t >> 5, l = t & 31;
    if (l == 0) { sh[0][w] = s0; sh[1][w] = q0; sh[2][w] = s1; sh[3][w] = q1; }
    __syncthreads();

    if (t < 2) {   // t=0 -> plane0, t=1 -> plane1
        float ts = 0.f, tq = 0.f;
        #pragma unroll
        for (int i = 0; i < 8; i++) { ts += sh[2 * t][i]; tq += sh[2 * t + 1][i]; }
        const int c = 2 * c2 + t;
        g_psum[c * B_ + b] = ts;
        g_psq [c * B_ + b] = tq;
    }
}

// ---------------------------------------------------------------------------
// Fold partials -> fused scale/bias. One block of 256 threads.
// ---------------------------------------------------------------------------
__global__ __launch_bounds__(256) void finalize_k(const float* __restrict__ gamma,
                                                  const float* __restrict__ beta) {
    const int c = threadIdx.x;
    float s = 0.f, sq = 0.f;
    #pragma unroll
    for (int b = 0; b < B_; b++) {
        s  += g_psum[c * B_ + b];
        sq += g_psq [c * B_ + b];
    }
    const float inv_n = 1.f / (float)NPC_;
    const float mean  = s * inv_n;
    const float var   = sq * inv_n - mean * mean;
    const float sc    = gamma[c] * rsqrtf(var + EPS_);
    g_scale[c] = sc;
    g_bias[c]  = beta[c] - mean * sc;
}

// ---------------------------------------------------------------------------
// Pass 2: flat elementwise, REVERSED block order (consume the L2-kept tail
// first). Reads __ldcs (hit-demote / no-pollute), stores __stcs (evict-first
// write-back — R15 showed WT is slower). 6272 blocks x 256 x 8 float4.
// ---------------------------------------------------------------------------
__global__ __launch_bounds__(256) void norm_k(const float4* __restrict__ x,
                                              float4* __restrict__ out) {
    const int base = (NBLK_ - 1 - (int)blockIdx.x) * 2048 + (int)threadIdx.x;

    float4 v[8];
    #pragma unroll
    for (int j = 0; j < 8; j++) v[j] = __ldcs(x + base + 256 * j);

    #pragma unroll
    for (int j = 0; j < 8; j++) {
        const int idx = base + 256 * j;
        const int c   = (idx / HW4_) & (C_ - 1);      // plane mod C
        const float sc = g_scale[c];
        const float bi = g_bias[c];
        v[j].x = fmaf(v[j].x, sc, bi);
        v[j].y = fmaf(v[j].y, sc, bi);
        v[j].z = fmaf(v[j].z, sc, bi);
        v[j].w = fmaf(v[j].w, sc, bi);
        __stcs(out + idx, v[j]);
    }
}

// ---------------------------------------------------------------------------
extern "C" void kernel_launch(void* const* d_in, const int* in_sizes, int n_in,
                              void* d_out, int out_size) {
    const float* x     = (const float*)d_in[0];
    const float* gamma = (const float*)d_in[1];
    const float* beta  = (const float*)d_in[2];
    float* out = (float*)d_out;

    dim3 rgrid(C_ / 2, B_);     // c2 fast, b slow -> execution ~ address order
    reduce_k<<<rgrid, 256>>>((const float4*)x);
    finalize_k<<<1, C_>>>(gamma, beta);
    norm_k<<<NBLK_, 256>>>((const float4*)x, (float4*)out);
}